// round 8
// baseline (speedup 1.0000x reference)
#include <cuda_runtime.h>
#include <cuda_bf16.h>
#include <stdint.h>

#define TPB 256

// ---------------- smem layout (bytes) ----------------
// Branch-phase double-buffered A tiles: [64 rows][256B], hi+lo each 16 KB
#define T_HI(b)   ((b) * 32768)
#define T_LO(b)   ((b) * 32768 + 16384)
// Phase-A chunk buffers alias the same region: [64 rows][128B], hi+lo each 8 KB
#define PA_HI(b)  ((b) * 32768)
#define PA_LO(b)  ((b) * 32768 + 8192)
#define OFF_BASE  65536          // fp32 base [64 rows][132 floats] = 33792 B
#define OFF_SB0   99328
#define OFF_SB1   99840
#define OFF_SB2   100352
#define OFF_SP    100864
#define OFF_SQ    101376
#define OFF_SB3   101888   // 64 B
#define OFF_LUT   101952   // 648 * 8 = 5184
#define SMEM_BYTES 107520

// ---------------- device weight images ----------------
// B-fragment packed, hi/lo INTERLEAVED per entry (uint4):
//   entry index = (kblk * nbStride + nblk) * 32 + lane
//   entry.x,.y = hi b-frag; entry.z,.w = lo b-frag
__device__ __align__(16) __nv_bfloat16 gW0[2 * 90112];  // 704 x 128 (44 kblk x 16 nblk)
__device__ __align__(16) __nv_bfloat16 gW1[2 * 16384];  // 128 x 128 (8 x 16)
__device__ __align__(16) __nv_bfloat16 gW2[2 * 16384];
__device__ __align__(16) __nv_bfloat16 gW3[2 * 2048];   // 128 x 16 (8 x 2)

// ---------------- asm helpers ----------------
__device__ __forceinline__ uint32_t smem_u32(const void* p) {
    uint32_t a;
    asm("{ .reg .u64 t; cvta.to.shared.u64 t, %1; cvt.u32.u64 %0, t; }" : "=r"(a) : "l"(p));
    return a;
}
__device__ __forceinline__ void ldmx4(uint32_t r[4], uint32_t addr) {
    asm volatile("ldmatrix.sync.aligned.m8n8.x4.shared.b16 {%0,%1,%2,%3}, [%4];"
        : "=r"(r[0]), "=r"(r[1]), "=r"(r[2]), "=r"(r[3]) : "r"(addr));
}
__device__ __forceinline__ void mma16816(float* d, const uint32_t a[4], uint32_t b0, uint32_t b1) {
    asm volatile("mma.sync.aligned.m16n8k16.row.col.f32.bf16.bf16.f32 "
        "{%0,%1,%2,%3}, {%4,%5,%6,%7}, {%8,%9}, {%0,%1,%2,%3};"
        : "+f"(d[0]), "+f"(d[1]), "+f"(d[2]), "+f"(d[3])
        : "r"(a[0]), "r"(a[1]), "r"(a[2]), "r"(a[3]), "r"(b0), "r"(b1));
}
__device__ __forceinline__ void split_pack(float v0, float v1, uint32_t& hi, uint32_t& lo) {
    __nv_bfloat16 h0 = __float2bfloat16(v0), h1 = __float2bfloat16(v1);
    float l0 = v0 - __bfloat162float(h0), l1 = v1 - __bfloat162float(h1);
    __nv_bfloat162 hp; hp.x = h0; hp.y = h1;
    __nv_bfloat162 lp; lp.x = __float2bfloat16(l0); lp.y = __float2bfloat16(l1);
    hi = *(uint32_t*)&hp; lo = *(uint32_t*)&lp;
}

// 3-term split GEMM; A (hi/lo) from swizzled smem via ldmatrix, B uint4 frags from global.
template<int KS, int MT, int NT, int RLOG>
__device__ __forceinline__ void gemm_gb(uint32_t aHi, uint32_t aLo,
    const uint4* __restrict__ gB,
    int kblk0, int nbStride, int nblk0, int mrow, float* acc, int lane)
{
    const int rA = mrow + (lane & 15);
    const int selA = lane >> 4;
    const uint32_t aHiRow = aHi + (rA << RLOG);
    const uint32_t aLoRow = aLo + (rA << RLOG);
    const int xorA = rA & 7;
    const uint4* b = gB + (kblk0 * nbStride + nblk0) * 32 + lane;
#pragma unroll
    for (int ks = 0; ks < KS; ks++) {
        const uint32_t offA = ((uint32_t)(((ks * 2 + selA) ^ xorA))) << 4;
        uint32_t ah[MT][4], al[MT][4];
#pragma unroll
        for (int mt = 0; mt < MT; mt++) {
            ldmx4(ah[mt], aHiRow + (mt << (RLOG + 4)) + offA);
            ldmx4(al[mt], aLoRow + (mt << (RLOG + 4)) + offA);
        }
        uint4 bv[NT];
#pragma unroll
        for (int nt = 0; nt < NT; nt++) bv[nt] = b[nt * 32];
        b += nbStride * 32;
#pragma unroll
        for (int nt = 0; nt < NT; nt++)
#pragma unroll
            for (int mt = 0; mt < MT; mt++) {
                float* d = acc + (mt * NT + nt) * 4;
                mma16816(d, ah[mt], bv[nt].x, bv[nt].y);
                mma16816(d, ah[mt], bv[nt].z, bv[nt].w);
                mma16816(d, al[mt], bv[nt].x, bv[nt].y);
            }
    }
}

// epilogue from register acc: (+bias) -> relu -> split bf16 -> swizzled smem tile
__device__ __forceinline__ void epi_acc(char* sm, uint32_t dstOff, const float* acc, const float* bias,
                                        int mg, int ng, int lane)
{
    const int rq = lane >> 2, nq = (lane & 3) * 2;
#pragma unroll
    for (int mt = 0; mt < 2; mt++) {
#pragma unroll
        for (int nt = 0; nt < 4; nt++) {
            int n = ng * 32 + nt * 8 + nq;
            float bb0 = bias[n], bb1 = bias[n + 1];
            const float* a = acc + (mt * 4 + nt) * 4;
#pragma unroll
            for (int half = 0; half < 2; half++) {
                int r = mg * 32 + mt * 16 + rq + half * 8;
                float v0 = fmaxf(a[half * 2 + 0] + bb0, 0.f);
                float v1 = fmaxf(a[half * 2 + 1] + bb1, 0.f);
                uint32_t hi, lo;
                split_pack(v0, v1, hi, lo);
                int off = (r << 8) + ((((n >> 3) ^ (r & 7)) << 4)) + (n & 7) * 2;
                *(uint32_t*)(sm + dstOff + off) = hi;
                *(uint32_t*)(sm + dstOff + 16384 + off) = lo;
            }
        }
    }
}

// h1 epilogue from smem base: base + b0 + s*(powv*P+Q) -> relu -> split -> tile
__device__ __forceinline__ void epi_base(char* sm, uint32_t dstOff, const float* sBase,
                                         const float* bias, float powv,
                                         const float* sP, const float* sQ,
                                         int mg, int ng, int lane, int hgrp)
{
    const int rq = lane >> 2, nq = (lane & 3) * 2;
#pragma unroll
    for (int mt = 0; mt < 2; mt++) {
#pragma unroll
        for (int nt = 0; nt < 4; nt++) {
            int n = ng * 32 + nt * 8 + nq;
            float bb0 = bias[n], bb1 = bias[n + 1];
            float e0 = fmaf(powv, sP[n], sQ[n]);
            float e1 = fmaf(powv, sP[n + 1], sQ[n + 1]);
#pragma unroll
            for (int half = 0; half < 2; half++) {
                int r = mg * 32 + mt * 16 + rq + half * 8;
                float s = 1.f;
                if (hgrp == 0 && r < 4) s = (r < 2) ? 0.0625f : (2.f / 7.f);
                float v0 = fmaxf(sBase[r * 132 + n] + bb0 + s * e0, 0.f);
                float v1 = fmaxf(sBase[r * 132 + n + 1] + bb1 + s * e1, 0.f);
                uint32_t hi, lo;
                split_pack(v0, v1, hi, lo);
                int off = (r << 8) + ((((n >> 3) ^ (r & 7)) << 4)) + (n & 7) * 2;
                *(uint32_t*)(sm + dstOff + off) = hi;
                *(uint32_t*)(sm + dstOff + 16384 + off) = lo;
            }
        }
    }
}

// ---------------- prep kernel ----------------
__device__ __forceinline__ void pack_frag(__nv_bfloat16* dst, float v, int k, int n, int nbStride) {
    __nv_bfloat16 h = __float2bfloat16(v);
    float lo = v - __bfloat162float(h);
    int entry = ((k >> 4) * nbStride + (n >> 3)) * 32 + (n & 7) * 4 + ((k >> 1) & 3);
    int sub = ((k >> 3) & 1) * 2 + (k & 1);
    dst[entry * 8 + sub] = h;
    dst[entry * 8 + 4 + sub] = __float2bfloat16(lo);
}

__global__ void prep_kernel(const float* __restrict__ W0, const float* __restrict__ W1,
                            const float* __restrict__ W2, const float* __restrict__ W3) {
    int idx = blockIdx.x * 256 + threadIdx.x;
    const int n0 = 90112, n1 = 16384, n2 = 16384, n3 = 2048;
    if (idx < n0) {
        int k = idx >> 7, n = idx & 127;
        float v = (k < 648) ? W0[k * 128 + n] : 0.f;
        pack_frag(gW0, v, k, n, 16);
    } else if (idx < n0 + n1) {
        int r = idx - n0, k = r >> 7, n = r & 127;
        pack_frag(gW1, W1[k * 128 + n], k, n, 16);
    } else if (idx < n0 + n1 + n2) {
        int r = idx - n0 - n1, k = r >> 7, n = r & 127;
        pack_frag(gW2, W2[k * 128 + n], k, n, 16);
    } else if (idx < n0 + n1 + n2 + n3) {
        int r = idx - n0 - n1 - n2, k = r >> 4, n = r & 15;
        float v = (n < 12) ? W3[k * 12 + n] : 0.f;
        pack_frag(gW3, v, k, n, 2);
    }
}

// ---------------- main kernel ----------------
__global__ __launch_bounds__(TPB, 2)
void inr_hmma_kernel(const float* __restrict__ inp,
                     const float* __restrict__ W0,
                     const float* __restrict__ b0g, const float* __restrict__ b1g,
                     const float* __restrict__ b2g, const float* __restrict__ b3g,
                     float* __restrict__ outp) {
    extern __shared__ char sm[];
    const uint32_t sbase = smem_u32(sm);
    const int tid = threadIdx.x;
    const int lane = tid & 31, w = tid >> 5;
    const int mg = w >> 2, ng = w & 3;      // 2 m-groups (32 rows) x 4 n-groups (32 cols)

    const int blk = blockIdx.x;
    const int ablk = blk >> 4, hgrp = blk & 15;   // 64 rows = 2 h-rows
    const int ahi = ablk / 7, awi = ablk % 7;
    const int inpBase = ahi * 7168 + awi * 1024 + hgrp * 64;

    float* sBase = (float*)(sm + OFF_BASE);
    float* sb0 = (float*)(sm + OFF_SB0);
    float* sb1 = (float*)(sm + OFF_SB1);
    float* sb2 = (float*)(sm + OFF_SB2);
    float* sP  = (float*)(sm + OFF_SP);
    float* sQ  = (float*)(sm + OFF_SQ);
    float* sb3 = (float*)(sm + OFF_SB3);
    int2*  lut = (int2*)(sm + OFF_LUT);

    for (int c = tid; c < 128; c += TPB) {
        sb0[c] = b0g[c]; sb1[c] = b1g[c]; sb2[c] = b2g[c];
        sP[c] = W0[716 * 128 + c] + W0[717 * 128 + c];
        sQ[c] = W0[718 * 128 + c] + W0[719 * 128 + c];
    }
    if (tid < 12) sb3[tid] = b3g[tid];
    for (int k = tid; k < 648; k += TPB) {
        int aj = k % 3, ai = (k / 3) % 3, kj = (k / 9) % 3, ki = (k / 27) % 3, ch = k / 81;
        int off = ch * 50176 + (ai - 1) * 7168 + (aj - 1) * 1024 + (ki - 1) * 32 + (kj - 1);
        lut[k] = make_int2(off, ai | (aj << 4) | (ki << 8) | (kj << 12));
    }
    __syncthreads();

    const uint4* gw0 = (const uint4*)gW0;
    const uint4* gw1 = (const uint4*)gW1;
    const uint4* gw2 = (const uint4*)gW2;
    const uint4* gw3 = (const uint4*)gW3;

    // ================= Phase A: base = q_feat @ W0 (11 chunks of K=64, ping-pong) ======
    float acc[32];
#pragma unroll
    for (int i = 0; i < 32; i++) acc[i] = 0.f;

    const int gm = tid & 63;
    const int gstrip = tid >> 6;
    const int ghi = hgrp * 2 + (gm >> 5), gwi = gm & 31;

    auto gather = [&](int c) {
        char* dh = sm + PA_HI(c & 1);
        char* dl = sm + PA_LO(c & 1);
#pragma unroll
        for (int q = 0; q < 8; q++) {
            int kp = gstrip * 8 + q;
            int kk = c * 64 + kp * 2;
            float v0 = 0.f, v1 = 0.f;
            if (kk < 648) {
                int2 lu = lut[kk];
                int ai = lu.y & 15, aj = (lu.y >> 4) & 15, ki = (lu.y >> 8) & 15, kj = (lu.y >> 12) & 15;
                bool ok = (unsigned)(ahi + ai - 1) < 7u && (unsigned)(awi + aj - 1) < 7u
                       && (unsigned)(ghi + ki - 1) < 32u && (unsigned)(gwi + kj - 1) < 32u;
                v0 = ok ? inp[inpBase + gm + lu.x] : 0.f;
            }
            if (kk + 1 < 648) {
                int2 lu = lut[kk + 1];
                int ai = lu.y & 15, aj = (lu.y >> 4) & 15, ki = (lu.y >> 8) & 15, kj = (lu.y >> 12) & 15;
                bool ok = (unsigned)(ahi + ai - 1) < 7u && (unsigned)(awi + aj - 1) < 7u
                       && (unsigned)(ghi + ki - 1) < 32u && (unsigned)(gwi + kj - 1) < 32u;
                v1 = ok ? inp[inpBase + gm + lu.x] : 0.f;
            }
            uint32_t hi, lo;
            split_pack(v0, v1, hi, lo);
            int off = gm * 128 + ((((kp >> 2) ^ (gm & 7)) << 4)) + (kp & 3) * 4;
            *(uint32_t*)(dh + off) = hi;
            *(uint32_t*)(dl + off) = lo;
        }
    };

    gather(0);
    __syncthreads();
    for (int c = 0; c < 11; c++) {
        if (c < 10) gather(c + 1);
        gemm_gb<4, 2, 4, 7>(sbase + PA_HI(c & 1), sbase + PA_LO(c & 1), gw0,
                            c * 4, 16, ng * 4, mg * 32, acc, lane);
        __syncthreads();
    }

    // ---- park base in smem (fp32, row stride 132 floats: conflict-free) ----
    {
        const int rq = lane >> 2, nq = (lane & 3) * 2;
#pragma unroll
        for (int mt = 0; mt < 2; mt++)
#pragma unroll
            for (int nt = 0; nt < 4; nt++) {
                int n = ng * 32 + nt * 8 + nq;
                const float* a = acc + (mt * 4 + nt) * 4;
#pragma unroll
                for (int half = 0; half < 2; half++) {
                    int r = mg * 32 + mt * 16 + rq + half * 8;
                    sBase[r * 132 + n]     = a[half * 2 + 0];
                    sBase[r * 132 + n + 1] = a[half * 2 + 1];
                }
            }
    }
    __syncthreads();

    // ================= 4 branches (ping-pong activation tiles) =================
    float y[8];
#pragma unroll
    for (int i = 0; i < 8; i++) y[i] = 0.f;
    float powv = 32.f;
    int p = 0;

    for (int br = 0; br < 4; br++) {
        // h1 = relu(base + b0 + s*(powv*P + Q)) -> buf p (base read from smem)
        epi_base(sm, T_HI(p), sBase, sb0, powv, sP, sQ, mg, ng, lane, hgrp);
        __syncthreads();

#pragma unroll
        for (int i = 0; i < 32; i++) acc[i] = 0.f;
        gemm_gb<8, 2, 4, 8>(sbase + T_HI(p), sbase + T_LO(p), gw1,
                            0, 16, ng * 4, mg * 32, acc, lane);
        // h2 -> buf p^1 (writes other buffer; no pre-sync needed)
        epi_acc(sm, T_HI(p ^ 1), acc, sb1, mg, ng, lane);
        __syncthreads();

#pragma unroll
        for (int i = 0; i < 32; i++) acc[i] = 0.f;
        gemm_gb<8, 2, 4, 8>(sbase + T_HI(p ^ 1), sbase + T_LO(p ^ 1), gw2,
                            0, 16, ng * 4, mg * 32, acc, lane);
        // h3 -> buf p
        epi_acc(sm, T_HI(p), acc, sb2, mg, ng, lane);
        __syncthreads();

        // y += h3 @ W3 (warps with ng<2; nblk = ng selects 8-col block of N=16)
        if (ng < 2) {
            gemm_gb<8, 2, 1, 8>(sbase + T_HI(p), sbase + T_LO(p), gw3,
                                0, 2, ng, mg * 32, y, lane);
        }
        p ^= 1;
        powv *= 32.f;
    }

    // ---- scatter (pixel shuffle); y = 0.25*sum + b3 ----
    if (ng < 2) {
        const int rq = lane >> 2, nq = (lane & 3) * 2;
#pragma unroll
        for (int mt = 0; mt < 2; mt++)
#pragma unroll
            for (int half = 0; half < 2; half++)
#pragma unroll
                for (int j = 0; j < 2; j++) {
                    int n = ng * 8 + nq + j;
                    if (n < 12) {
                        int r = mg * 32 + mt * 16 + rq + half * 8;
                        float val = 0.25f * y[mt * 4 + half * 2 + j] + sb3[n];
                        int hi = hgrp * 2 + (r >> 5), wi = r & 31;
                        int rgb = n >> 2, pr = (n >> 1) & 1, qc = n & 1;
                        outp[rgb * 200704 + ahi * 28672 + awi * 4096 +
                             (2 * hi + pr) * 64 + (2 * wi + qc)] = val;
                    }
                }
    }
}

extern "C" void kernel_launch(void* const* d_in, const int* in_sizes, int n_in,
                              void* d_out, int out_size) {
    (void)in_sizes; (void)n_in; (void)out_size;
    const float* inp = (const float*)d_in[0];
    const float* W0  = (const float*)d_in[1];
    const float* b0  = (const float*)d_in[2];
    const float* W1  = (const float*)d_in[3];
    const float* b1  = (const float*)d_in[4];
    const float* W2  = (const float*)d_in[5];
    const float* b2  = (const float*)d_in[6];
    const float* W3  = (const float*)d_in[7];
    const float* b3  = (const float*)d_in[8];
    float* outp = (float*)d_out;

    const int prep_tasks = 90112 + 16384 + 16384 + 2048;
    prep_kernel<<<(prep_tasks + 255) / 256, 256>>>(W0, W1, W2, W3);

    cudaFuncSetAttribute(inr_hmma_kernel, cudaFuncAttributeMaxDynamicSharedMemorySize, SMEM_BYTES);
    inr_hmma_kernel<<<784, TPB, SMEM_BYTES>>>(inp, W0, b0, b1, b2, b3, outp);
}

// round 9
// speedup vs baseline: 1.3329x; 1.3329x over previous
#include <cuda_runtime.h>
#include <cuda_fp16.h>
#include <stdint.h>

#define TPB 256

// ---------------- smem layout (bytes) ----------------
// Branch-phase double-buffered A tiles: [64 rows][256B], hi+lo each 16 KB
#define T_HI(b)   ((b) * 32768)
#define T_LO(b)   ((b) * 32768 + 16384)
// Phase-A chunk buffers alias the same region: [64 rows][128B], hi+lo each 8 KB
#define PA_HI(b)  ((b) * 32768)
#define PA_LO(b)  ((b) * 32768 + 8192)
#define OFF_SB0   65536
#define OFF_SB1   66048
#define OFF_SB2   66560
#define OFF_SP    67072
#define OFF_SQ    67584
#define OFF_SB3   68096    // 64 B
#define OFF_LUT   68160    // 648 * 8
#define SMEM_BYTES 73728

// activation pre-scale (keeps branch-3 h1 within fp16 range)
#define ASCL   0.0625f     // 1/16
#define ASCL_I 16.0f

// ---------------- device weight images ----------------
// Single-fp16 B-fragment packed (uint2 per lane entry):
//   entry index = (kblk * nbStride + nblk) * 32 + lane,  lane = (n&7)*4 + ((k>>1)&3)
//   half within entry: ((k>>3)&1)*2 + (k&1)
__device__ __align__(16) __half gW0[90112];  // 704 x 128 (44 kblk x 16 nblk)
__device__ __align__(16) __half gW1[16384];  // 128 x 128 (8 x 16)
__device__ __align__(16) __half gW2[16384];
__device__ __align__(16) __half gW3[2048];   // 128 x 16 (8 x 2)

// ---------------- asm helpers ----------------
__device__ __forceinline__ uint32_t smem_u32(const void* p) {
    uint32_t a;
    asm("{ .reg .u64 t; cvta.to.shared.u64 t, %1; cvt.u32.u64 %0, t; }" : "=r"(a) : "l"(p));
    return a;
}
__device__ __forceinline__ void ldmx4(uint32_t r[4], uint32_t addr) {
    asm volatile("ldmatrix.sync.aligned.m8n8.x4.shared.b16 {%0,%1,%2,%3}, [%4];"
        : "=r"(r[0]), "=r"(r[1]), "=r"(r[2]), "=r"(r[3]) : "r"(addr));
}
__device__ __forceinline__ void mma16816(float* d, const uint32_t a[4], uint32_t b0, uint32_t b1) {
    asm volatile("mma.sync.aligned.m16n8k16.row.col.f32.f16.f16.f32 "
        "{%0,%1,%2,%3}, {%4,%5,%6,%7}, {%8,%9}, {%0,%1,%2,%3};"
        : "+f"(d[0]), "+f"(d[1]), "+f"(d[2]), "+f"(d[3])
        : "r"(a[0]), "r"(a[1]), "r"(a[2]), "r"(a[3]), "r"(b0), "r"(b1));
}
// scale, then 2-term fp16 split (hi + lo covers ~22 mantissa bits)
__device__ __forceinline__ void split_pack(float v0, float v1, float sc, uint32_t& hi, uint32_t& lo) {
    float a0 = v0 * sc, a1 = v1 * sc;
    __half h0 = __float2half_rn(a0), h1 = __float2half_rn(a1);
    float l0 = a0 - __half2float(h0), l1 = a1 - __half2float(h1);
    __half2 hp = __halves2half2(h0, h1);
    __half2 lp = __halves2half2(__float2half_rn(l0), __float2half_rn(l1));
    hi = *(uint32_t*)&hp; lo = *(uint32_t*)&lp;
}

// 2-term split GEMM; A (hi/lo fp16) from swizzled smem via ldmatrix, B uint2 frags from global.
// Warp computes rows [mrow, mrow+16*MT) x cols [nblk0*8, (nblk0+NT)*8).
template<int KS, int MT, int NT, int RLOG>
__device__ __forceinline__ void gemm_gb(uint32_t aHi, uint32_t aLo,
    const uint2* __restrict__ gB,
    int kblk0, int nbStride, int nblk0, int mrow, float* acc, int lane)
{
    const int rA = mrow + (lane & 15);
    const int selA = lane >> 4;
    const uint32_t aHiRow = aHi + (rA << RLOG);
    const uint32_t aLoRow = aLo + (rA << RLOG);
    const int xorA = rA & 7;
    const uint2* b = gB + (kblk0 * nbStride + nblk0) * 32 + lane;
#pragma unroll
    for (int ks = 0; ks < KS; ks++) {
        const uint32_t offA = ((uint32_t)(((ks * 2 + selA) ^ xorA))) << 4;
        uint32_t ah[MT][4], al[MT][4];
#pragma unroll
        for (int mt = 0; mt < MT; mt++) {
            ldmx4(ah[mt], aHiRow + (mt << (RLOG + 4)) + offA);
            ldmx4(al[mt], aLoRow + (mt << (RLOG + 4)) + offA);
        }
        uint2 bv[NT];
#pragma unroll
        for (int nt = 0; nt < NT; nt++) bv[nt] = b[nt * 32];
        b += nbStride * 32;
#pragma unroll
        for (int nt = 0; nt < NT; nt++)
#pragma unroll
            for (int mt = 0; mt < MT; mt++) {
                float* d = acc + (mt * NT + nt) * 4;
                mma16816(d, ah[mt], bv[nt].x, bv[nt].y);
                mma16816(d, al[mt], bv[nt].x, bv[nt].y);
            }
    }
}

// epilogue: D frags (ASCL_I*acc + bias [+cell term]) -> relu -> fp16 split (xASCL) -> smem tile
// warp tile: rows mg*32 + mt*16 + rq(+8), cols ng*32 + nt*8 + nq
template<bool EXTRA, bool RESCALE>
__device__ __forceinline__ void epi(char* sm, uint32_t dstOff, const float* acc, const float* bias,
                                    float powv, const float* sP, const float* sQ,
                                    int mg, int ng, int lane, int hgrp)
{
    const int rq = lane >> 2, nq = (lane & 3) * 2;
#pragma unroll
    for (int mt = 0; mt < 2; mt++) {
#pragma unroll
        for (int nt = 0; nt < 4; nt++) {
            int n = ng * 32 + nt * 8 + nq;
            float bb0 = bias[n], bb1 = bias[n + 1];
            float e0 = 0.f, e1 = 0.f;
            if (EXTRA) { e0 = fmaf(powv, sP[n], sQ[n]); e1 = fmaf(powv, sP[n + 1], sQ[n + 1]); }
            const float* a = acc + (mt * 4 + nt) * 4;
#pragma unroll
            for (int half = 0; half < 2; half++) {
                int r = mg * 32 + mt * 16 + rq + half * 8;
                float av0 = RESCALE ? ASCL_I * a[half * 2 + 0] : a[half * 2 + 0];
                float av1 = RESCALE ? ASCL_I * a[half * 2 + 1] : a[half * 2 + 1];
                float v0 = av0 + bb0;
                float v1 = av1 + bb1;
                if (EXTRA) {
                    float s = 1.f;
                    if (hgrp == 0 && r < 4) s = (r < 2) ? 0.0625f : (2.f / 7.f);
                    v0 += s * e0; v1 += s * e1;
                }
                v0 = fmaxf(v0, 0.f); v1 = fmaxf(v1, 0.f);
                uint32_t hi, lo;
                split_pack(v0, v1, ASCL, hi, lo);
                int off = (r << 8) + ((((n >> 3) ^ (r & 7)) << 4)) + (n & 7) * 2;
                *(uint32_t*)(sm + dstOff + off) = hi;
                *(uint32_t*)(sm + dstOff + 16384 + off) = lo;
            }
        }
    }
}

// ---------------- prep kernel: quantize weights to fp16 B-frag layout ----------------
__device__ __forceinline__ void pack_frag(__half* dst, float v, int k, int n, int nbStride) {
    int entry = ((k >> 4) * nbStride + (n >> 3)) * 32 + (n & 7) * 4 + ((k >> 1) & 3);
    int sub = ((k >> 3) & 1) * 2 + (k & 1);
    dst[entry * 4 + sub] = __float2half_rn(v);
}

__global__ void prep_kernel(const float* __restrict__ W0, const float* __restrict__ W1,
                            const float* __restrict__ W2, const float* __restrict__ W3) {
    int idx = blockIdx.x * 256 + threadIdx.x;
    const int n0 = 90112, n1 = 16384, n2 = 16384, n3 = 2048;
    if (idx < n0) {
        int k = idx >> 7, n = idx & 127;
        float v = (k < 648) ? W0[k * 128 + n] : 0.f;
        pack_frag(gW0, v, k, n, 16);
    } else if (idx < n0 + n1) {
        int r = idx - n0, k = r >> 7, n = r & 127;
        pack_frag(gW1, W1[k * 128 + n], k, n, 16);
    } else if (idx < n0 + n1 + n2) {
        int r = idx - n0 - n1, k = r >> 7, n = r & 127;
        pack_frag(gW2, W2[k * 128 + n], k, n, 16);
    } else if (idx < n0 + n1 + n2 + n3) {
        int r = idx - n0 - n1 - n2, k = r >> 4, n = r & 15;
        float v = (n < 12) ? W3[k * 12 + n] : 0.f;
        pack_frag(gW3, v, k, n, 2);
    }
}

// ---------------- main kernel ----------------
__global__ __launch_bounds__(TPB, 2)
void inr_hmma_kernel(const float* __restrict__ inp,
                     const float* __restrict__ W0,
                     const float* __restrict__ b0g, const float* __restrict__ b1g,
                     const float* __restrict__ b2g, const float* __restrict__ b3g,
                     float* __restrict__ outp) {
    extern __shared__ char sm[];
    const uint32_t sbase = smem_u32(sm);
    const int tid = threadIdx.x;
    const int lane = tid & 31, w = tid >> 5;
    const int mg = w >> 2, ng = w & 3;      // 2 m-groups (32 rows) x 4 n-groups (32 cols)

    const int blk = blockIdx.x;
    const int ablk = blk >> 4, hgrp = blk & 15;   // 64 rows = 2 h-rows
    const int ahi = ablk / 7, awi = ablk % 7;
    const int inpBase = ahi * 7168 + awi * 1024 + hgrp * 64;

    float* sb0 = (float*)(sm + OFF_SB0);
    float* sb1 = (float*)(sm + OFF_SB1);
    float* sb2 = (float*)(sm + OFF_SB2);
    float* sP  = (float*)(sm + OFF_SP);
    float* sQ  = (float*)(sm + OFF_SQ);
    float* sb3 = (float*)(sm + OFF_SB3);
    int2*  lut = (int2*)(sm + OFF_LUT);

    for (int c = tid; c < 128; c += TPB) {
        sb0[c] = b0g[c]; sb1[c] = b1g[c]; sb2[c] = b2g[c];
        sP[c] = W0[716 * 128 + c] + W0[717 * 128 + c];
        sQ[c] = W0[718 * 128 + c] + W0[719 * 128 + c];
    }
    if (tid < 12) sb3[tid] = b3g[tid];
    for (int k = tid; k < 648; k += TPB) {
        int aj = k % 3, ai = (k / 3) % 3, kj = (k / 9) % 3, ki = (k / 27) % 3, ch = k / 81;
        int off = ch * 50176 + (ai - 1) * 7168 + (aj - 1) * 1024 + (ki - 1) * 32 + (kj - 1);
        lut[k] = make_int2(off, ai | (aj << 4) | (ki << 8) | (kj << 12));
    }
    __syncthreads();

    const uint2* gw0 = (const uint2*)gW0;
    const uint2* gw1 = (const uint2*)gW1;
    const uint2* gw2 = (const uint2*)gW2;
    const uint2* gw3 = (const uint2*)gW3;

    // ================= Phase A: base = q_feat @ W0 (11 chunks of K=64, ping-pong) ======
    float base_[32];
#pragma unroll
    for (int i = 0; i < 32; i++) base_[i] = 0.f;

    const int gm = tid & 63;          // row (position)
    const int gstrip = tid >> 6;      // k-pair strip
    const int ghi = hgrp * 2 + (gm >> 5), gwi = gm & 31;

    auto gather = [&](int c) {
        char* dh = sm + PA_HI(c & 1);
        char* dl = sm + PA_LO(c & 1);
#pragma unroll
        for (int q = 0; q < 8; q++) {
            int kp = gstrip * 8 + q;
            int kk = c * 64 + kp * 2;
            float v0 = 0.f, v1 = 0.f;
            if (kk < 648) {
                int2 lu = lut[kk];
                int ai = lu.y & 15, aj = (lu.y >> 4) & 15, ki = (lu.y >> 8) & 15, kj = (lu.y >> 12) & 15;
                bool ok = (unsigned)(ahi + ai - 1) < 7u && (unsigned)(awi + aj - 1) < 7u
                       && (unsigned)(ghi + ki - 1) < 32u && (unsigned)(gwi + kj - 1) < 32u;
                v0 = ok ? inp[inpBase + gm + lu.x] : 0.f;
            }
            if (kk + 1 < 648) {
                int2 lu = lut[kk + 1];
                int ai = lu.y & 15, aj = (lu.y >> 4) & 15, ki = (lu.y >> 8) & 15, kj = (lu.y >> 12) & 15;
                bool ok = (unsigned)(ahi + ai - 1) < 7u && (unsigned)(awi + aj - 1) < 7u
                       && (unsigned)(ghi + ki - 1) < 32u && (unsigned)(gwi + kj - 1) < 32u;
                v1 = ok ? inp[inpBase + gm + lu.x] : 0.f;
            }
            uint32_t hi, lo;
            split_pack(v0, v1, 1.f, hi, lo);    // inputs ~N(0,1): no scaling needed
            int off = gm * 128 + ((((kp >> 2) ^ (gm & 7)) << 4)) + (kp & 3) * 4;
            *(uint32_t*)(dh + off) = hi;
            *(uint32_t*)(dl + off) = lo;
        }
    };

    gather(0);
    __syncthreads();
    for (int c = 0; c < 11; c++) {
        if (c < 10) gather(c + 1);
        gemm_gb<4, 2, 4, 7>(sbase + PA_HI(c & 1), sbase + PA_LO(c & 1), gw0,
                            c * 4, 16, ng * 4, mg * 32, base_, lane);
        __syncthreads();
    }

    // ================= 4 branches (ping-pong activation tiles) =================
    float y[8];
#pragma unroll
    for (int i = 0; i < 8; i++) y[i] = 0.f;
    float powv = 32.f;
    int p = 0;

    for (int br = 0; br < 4; br++) {
        // h1 = relu(base + b0 + s*(powv*P + Q)) -> buf p   (base unscaled: RESCALE=false)
        epi<true, false>(sm, T_HI(p), base_, sb0, powv, sP, sQ, mg, ng, lane, hgrp);
        __syncthreads();

        float acc[32];
#pragma unroll
        for (int i = 0; i < 32; i++) acc[i] = 0.f;
        gemm_gb<8, 2, 4, 8>(sbase + T_HI(p), sbase + T_LO(p), gw1,
                            0, 16, ng * 4, mg * 32, acc, lane);
        // h2 -> buf p^1 (acc scaled by 1/16: RESCALE=true)
        epi<false, true>(sm, T_HI(p ^ 1), acc, sb1, 0.f, sP, sQ, mg, ng, lane, hgrp);
        __syncthreads();

#pragma unroll
        for (int i = 0; i < 32; i++) acc[i] = 0.f;
        gemm_gb<8, 2, 4, 8>(sbase + T_HI(p ^ 1), sbase + T_LO(p ^ 1), gw2,
                            0, 16, ng * 4, mg * 32, acc, lane);
        // h3 -> buf p
        epi<false, true>(sm, T_HI(p), acc, sb2, 0.f, sP, sQ, mg, ng, lane, hgrp);
        __syncthreads();

        // y += (h3/16) @ W3 (warps with ng<2; nblk = ng selects 8-col block of N=16)
        if (ng < 2) {
            gemm_gb<8, 2, 1, 8>(sbase + T_HI(p), sbase + T_LO(p), gw3,
                                0, 2, ng, mg * 32, y, lane);
        }
        p ^= 1;
        powv *= 32.f;
    }

    // ---- scatter (pixel shuffle); y_true = 16*y, out = 0.25*sum + b3 = 4*y + b3 ----
    if (ng < 2) {
        const int rq = lane >> 2, nq = (lane & 3) * 2;
#pragma unroll
        for (int mt = 0; mt < 2; mt++)
#pragma unroll
            for (int half = 0; half < 2; half++)
#pragma unroll
                for (int j = 0; j < 2; j++) {
                    int n = ng * 8 + nq + j;
                    if (n < 12) {
                        int r = mg * 32 + mt * 16 + rq + half * 8;
                        float val = 4.0f * y[mt * 4 + half * 2 + j] + sb3[n];
                        int hi = hgrp * 2 + (r >> 5), wi = r & 31;
                        int rgb = n >> 2, pr = (n >> 1) & 1, qc = n & 1;
                        outp[rgb * 200704 + ahi * 28672 + awi * 4096 +
                             (2 * hi + pr) * 64 + (2 * wi + qc)] = val;
                    }
                }
    }
}

extern "C" void kernel_launch(void* const* d_in, const int* in_sizes, int n_in,
                              void* d_out, int out_size) {
    (void)in_sizes; (void)n_in; (void)out_size;
    const float* inp = (const float*)d_in[0];
    const float* W0  = (const float*)d_in[1];
    const float* b0  = (const float*)d_in[2];
    const float* W1  = (const float*)d_in[3];
    const float* b1  = (const float*)d_in[4];
    const float* W2  = (const float*)d_in[5];
    const float* b2  = (const float*)d_in[6];
    const float* W3  = (const float*)d_in[7];
    const float* b3  = (const float*)d_in[8];
    float* outp = (float*)d_out;

    const int prep_tasks = 90112 + 16384 + 16384 + 2048;
    prep_kernel<<<(prep_tasks + 255) / 256, 256>>>(W0, W1, W2, W3);

    cudaFuncSetAttribute(inr_hmma_kernel, cudaFuncAttributeMaxDynamicSharedMemorySize, SMEM_BYTES);
    inr_hmma_kernel<<<784, TPB, SMEM_BYTES>>>(inp, W0, b0, b1, b2, b3, outp);
}

// round 10
// speedup vs baseline: 1.6786x; 1.2594x over previous
#include <cuda_runtime.h>
#include <cuda_fp16.h>
#include <stdint.h>

#define TPB 256

// ---------------- smem layout (bytes) ----------------
// Branch-phase double-buffered A tiles (hi only): [64 rows][256B] = 16 KB each
#define T_BUF(b)  ((b) * 16384)
// Phase-A chunk buffers alias the same 32 KB region: [64 rows][128B], hi+lo 8 KB each
#define PA_HI(b)  ((b) * 16384)
#define PA_LO(b)  ((b) * 16384 + 8192)
#define OFF_SB0   32768
#define OFF_SB1   33280
#define OFF_SB2   33792
#define OFF_SP    34304
#define OFF_SQ    34816
#define OFF_SB3   35328    // 64 B
#define OFF_LUT   35392    // 648 * 8 = 5184
#define SMEM_BYTES 40960

// activation pre-scale (keeps branch-3 h1 within fp16 range)
#define ASCL   0.0625f     // 1/16
#define ASCL_I 16.0f

// ---------------- device weight images ----------------
// Single-fp16 B-fragment packed (uint2 per lane entry):
//   entry index = (kblk * nbStride + nblk) * 32 + lane,  lane = (n&7)*4 + ((k>>1)&3)
//   half within entry: ((k>>3)&1)*2 + (k&1)
__device__ __align__(16) __half gW0[90112];  // 704 x 128 (44 kblk x 16 nblk)
__device__ __align__(16) __half gW1[16384];  // 128 x 128 (8 x 16)
__device__ __align__(16) __half gW2[16384];
__device__ __align__(16) __half gW3[2048];   // 128 x 16 (8 x 2)

// ---------------- asm helpers ----------------
__device__ __forceinline__ uint32_t smem_u32(const void* p) {
    uint32_t a;
    asm("{ .reg .u64 t; cvta.to.shared.u64 t, %1; cvt.u32.u64 %0, t; }" : "=r"(a) : "l"(p));
    return a;
}
__device__ __forceinline__ void ldmx4(uint32_t r[4], uint32_t addr) {
    asm volatile("ldmatrix.sync.aligned.m8n8.x4.shared.b16 {%0,%1,%2,%3}, [%4];"
        : "=r"(r[0]), "=r"(r[1]), "=r"(r[2]), "=r"(r[3]) : "r"(addr));
}
__device__ __forceinline__ void mma16816(float* d, const uint32_t a[4], uint32_t b0, uint32_t b1) {
    asm volatile("mma.sync.aligned.m16n8k16.row.col.f32.f16.f16.f32 "
        "{%0,%1,%2,%3}, {%4,%5,%6,%7}, {%8,%9}, {%0,%1,%2,%3};"
        : "+f"(d[0]), "+f"(d[1]), "+f"(d[2]), "+f"(d[3])
        : "r"(a[0]), "r"(a[1]), "r"(a[2]), "r"(a[3]), "r"(b0), "r"(b1));
}
// 2-term fp16 split (phase-A inputs)
__device__ __forceinline__ void split_pack(float v0, float v1, uint32_t& hi, uint32_t& lo) {
    __half h0 = __float2half_rn(v0), h1 = __float2half_rn(v1);
    float l0 = v0 - __half2float(h0), l1 = v1 - __half2float(h1);
    __half2 hp = __halves2half2(h0, h1);
    __half2 lp = __halves2half2(__float2half_rn(l0), __float2half_rn(l1));
    hi = *(uint32_t*)&hp; lo = *(uint32_t*)&lp;
}

// GEMM: A from swizzled smem via ldmatrix (optionally 2-term hi/lo), B uint2 frags from global.
// Warp computes rows [mrow, mrow+16*MT) x cols [nblk0*8, (nblk0+NT)*8).
template<int KS, int MT, int NT, int RLOG, bool LO>
__device__ __forceinline__ void gemm_gb(uint32_t aHi, uint32_t aLo,
    const uint2* __restrict__ gB,
    int kblk0, int nbStride, int nblk0, int mrow, float* acc, int lane)
{
    const int rA = mrow + (lane & 15);
    const int selA = lane >> 4;
    const uint32_t aHiRow = aHi + (rA << RLOG);
    const uint32_t aLoRow = aLo + (rA << RLOG);
    const int xorA = rA & 7;
    const uint2* b = gB + (kblk0 * nbStride + nblk0) * 32 + lane;
#pragma unroll
    for (int ks = 0; ks < KS; ks++) {
        const uint32_t offA = ((uint32_t)(((ks * 2 + selA) ^ xorA))) << 4;
        uint32_t ah[MT][4], al[MT][4];
#pragma unroll
        for (int mt = 0; mt < MT; mt++) {
            ldmx4(ah[mt], aHiRow + (mt << (RLOG + 4)) + offA);
            if (LO) ldmx4(al[mt], aLoRow + (mt << (RLOG + 4)) + offA);
        }
        uint2 bv[NT];
#pragma unroll
        for (int nt = 0; nt < NT; nt++) bv[nt] = b[nt * 32];
        b += nbStride * 32;
#pragma unroll
        for (int nt = 0; nt < NT; nt++)
#pragma unroll
            for (int mt = 0; mt < MT; mt++) {
                float* d = acc + (mt * NT + nt) * 4;
                mma16816(d, ah[mt], bv[nt].x, bv[nt].y);
                if (LO) mma16816(d, al[mt], bv[nt].x, bv[nt].y);
            }
    }
}

// epilogue: D frags (ASCL_I*acc + bias [+cell term]) -> relu -> fp16 (xASCL) -> smem hi tile
// warp tile: rows mg*32 + mt*16 + rq(+8), cols ng*32 + nt*8 + nq
template<bool EXTRA, bool RESCALE>
__device__ __forceinline__ void epi(char* sm, uint32_t dstOff, const float* acc, const float* bias,
                                    float powv, const float* sP, const float* sQ,
                                    int mg, int ng, int lane, int hgrp)
{
    const int rq = lane >> 2, nq = (lane & 3) * 2;
#pragma unroll
    for (int mt = 0; mt < 2; mt++) {
#pragma unroll
        for (int nt = 0; nt < 4; nt++) {
            int n = ng * 32 + nt * 8 + nq;
            float bb0 = bias[n], bb1 = bias[n + 1];
            float e0 = 0.f, e1 = 0.f;
            if (EXTRA) { e0 = fmaf(powv, sP[n], sQ[n]); e1 = fmaf(powv, sP[n + 1], sQ[n + 1]); }
            const float* a = acc + (mt * 4 + nt) * 4;
#pragma unroll
            for (int half = 0; half < 2; half++) {
                int r = mg * 32 + mt * 16 + rq + half * 8;
                float av0 = RESCALE ? ASCL_I * a[half * 2 + 0] : a[half * 2 + 0];
                float av1 = RESCALE ? ASCL_I * a[half * 2 + 1] : a[half * 2 + 1];
                float v0 = av0 + bb0;
                float v1 = av1 + bb1;
                if (EXTRA) {
                    float s = 1.f;
                    if (hgrp == 0 && r < 4) s = (r < 2) ? 0.0625f : (2.f / 7.f);
                    v0 += s * e0; v1 += s * e1;
                }
                v0 = fmaxf(v0, 0.f) * ASCL;
                v1 = fmaxf(v1, 0.f) * ASCL;
                __half2 hp = __floats2half2_rn(v0, v1);
                int off = (r << 8) + ((((n >> 3) ^ (r & 7)) << 4)) + (n & 7) * 2;
                *(uint32_t*)(sm + dstOff + off) = *(uint32_t*)&hp;
            }
        }
    }
}

// ---------------- prep kernel: quantize weights to fp16 B-frag layout ----------------
__device__ __forceinline__ void pack_frag(__half* dst, float v, int k, int n, int nbStride) {
    int entry = ((k >> 4) * nbStride + (n >> 3)) * 32 + (n & 7) * 4 + ((k >> 1) & 3);
    int sub = ((k >> 3) & 1) * 2 + (k & 1);
    dst[entry * 4 + sub] = __float2half_rn(v);
}

__global__ void prep_kernel(const float* __restrict__ W0, const float* __restrict__ W1,
                            const float* __restrict__ W2, const float* __restrict__ W3) {
    int idx = blockIdx.x * 256 + threadIdx.x;
    const int n0 = 90112, n1 = 16384, n2 = 16384, n3 = 2048;
    if (idx < n0) {
        int k = idx >> 7, n = idx & 127;
        float v = (k < 648) ? W0[k * 128 + n] : 0.f;
        pack_frag(gW0, v, k, n, 16);
    } else if (idx < n0 + n1) {
        int r = idx - n0, k = r >> 7, n = r & 127;
        pack_frag(gW1, W1[k * 128 + n], k, n, 16);
    } else if (idx < n0 + n1 + n2) {
        int r = idx - n0 - n1, k = r >> 7, n = r & 127;
        pack_frag(gW2, W2[k * 128 + n], k, n, 16);
    } else if (idx < n0 + n1 + n2 + n3) {
        int r = idx - n0 - n1 - n2, k = r >> 4, n = r & 15;
        float v = (n < 12) ? W3[k * 12 + n] : 0.f;
        pack_frag(gW3, v, k, n, 2);
    }
}

// ---------------- main kernel ----------------
__global__ __launch_bounds__(TPB, 2)
void inr_hmma_kernel(const float* __restrict__ inp,
                     const float* __restrict__ W0,
                     const float* __restrict__ b0g, const float* __restrict__ b1g,
                     const float* __restrict__ b2g, const float* __restrict__ b3g,
                     float* __restrict__ outp) {
    extern __shared__ char sm[];
    const uint32_t sbase = smem_u32(sm);
    const int tid = threadIdx.x;
    const int lane = tid & 31, w = tid >> 5;
    const int mg = w >> 2, ng = w & 3;      // 2 m-groups (32 rows) x 4 n-groups (32 cols)

    const int blk = blockIdx.x;
    const int ablk = blk >> 4, hgrp = blk & 15;   // 64 rows = 2 h-rows
    const int ahi = ablk / 7, awi = ablk % 7;
    const int inpBase = ahi * 7168 + awi * 1024 + hgrp * 64;

    float* sb0 = (float*)(sm + OFF_SB0);
    float* sb1 = (float*)(sm + OFF_SB1);
    float* sb2 = (float*)(sm + OFF_SB2);
    float* sP  = (float*)(sm + OFF_SP);
    float* sQ  = (float*)(sm + OFF_SQ);
    float* sb3 = (float*)(sm + OFF_SB3);
    int2*  lut = (int2*)(sm + OFF_LUT);

    for (int c = tid; c < 128; c += TPB) {
        sb0[c] = b0g[c]; sb1[c] = b1g[c]; sb2[c] = b2g[c];
        sP[c] = W0[716 * 128 + c] + W0[717 * 128 + c];
        sQ[c] = W0[718 * 128 + c] + W0[719 * 128 + c];
    }
    if (tid < 12) sb3[tid] = b3g[tid];
    for (int k = tid; k < 648; k += TPB) {
        int aj = k % 3, ai = (k / 3) % 3, kj = (k / 9) % 3, ki = (k / 27) % 3, ch = k / 81;
        int off = ch * 50176 + (ai - 1) * 7168 + (aj - 1) * 1024 + (ki - 1) * 32 + (kj - 1);
        lut[k] = make_int2(off, ai | (aj << 4) | (ki << 8) | (kj << 12));
    }
    __syncthreads();

    const uint2* gw0 = (const uint2*)gW0;
    const uint2* gw1 = (const uint2*)gW1;
    const uint2* gw2 = (const uint2*)gW2;
    const uint2* gw3 = (const uint2*)gW3;

    // ================= Phase A: base = q_feat @ W0 (11 chunks of K=64, ping-pong, 2-term) ====
    float base_[32];
#pragma unroll
    for (int i = 0; i < 32; i++) base_[i] = 0.f;

    const int gm = tid & 63;          // row (position)
    const int gstrip = tid >> 6;      // k-pair strip
    const int ghi = hgrp * 2 + (gm >> 5), gwi = gm & 31;

    auto gather = [&](int c) {
        char* dh = sm + PA_HI(c & 1);
        char* dl = sm + PA_LO(c & 1);
#pragma unroll
        for (int q = 0; q < 8; q++) {
            int kp = gstrip * 8 + q;
            int kk = c * 64 + kp * 2;
            float v0 = 0.f, v1 = 0.f;
            if (kk < 648) {
                int2 lu = lut[kk];
                int ai = lu.y & 15, aj = (lu.y >> 4) & 15, ki = (lu.y >> 8) & 15, kj = (lu.y >> 12) & 15;
                bool ok = (unsigned)(ahi + ai - 1) < 7u && (unsigned)(awi + aj - 1) < 7u
                       && (unsigned)(ghi + ki - 1) < 32u && (unsigned)(gwi + kj - 1) < 32u;
                v0 = ok ? inp[inpBase + gm + lu.x] : 0.f;
            }
            if (kk + 1 < 648) {
                int2 lu = lut[kk + 1];
                int ai = lu.y & 15, aj = (lu.y >> 4) & 15, ki = (lu.y >> 8) & 15, kj = (lu.y >> 12) & 15;
                bool ok = (unsigned)(ahi + ai - 1) < 7u && (unsigned)(awi + aj - 1) < 7u
                       && (unsigned)(ghi + ki - 1) < 32u && (unsigned)(gwi + kj - 1) < 32u;
                v1 = ok ? inp[inpBase + gm + lu.x] : 0.f;
            }
            uint32_t hi, lo;
            split_pack(v0, v1, hi, lo);
            int off = gm * 128 + ((((kp >> 2) ^ (gm & 7)) << 4)) + (kp & 3) * 4;
            *(uint32_t*)(dh + off) = hi;
            *(uint32_t*)(dl + off) = lo;
        }
    };

    gather(0);
    __syncthreads();
    for (int c = 0; c < 11; c++) {
        if (c < 10) gather(c + 1);
        gemm_gb<4, 2, 4, 7, true>(sbase + PA_HI(c & 1), sbase + PA_LO(c & 1), gw0,
                                  c * 4, 16, ng * 4, mg * 32, base_, lane);
        __syncthreads();
    }

    // ================= 4 branches (ping-pong hi-only activation tiles, 1-term) =================
    float y[8];
#pragma unroll
    for (int i = 0; i < 8; i++) y[i] = 0.f;
    float powv = 32.f;
    int p = 0;

    for (int br = 0; br < 4; br++) {
        // h1 = relu(base + b0 + s*(powv*P + Q)) -> buf p   (base unscaled: RESCALE=false)
        epi<true, false>(sm, T_BUF(p), base_, sb0, powv, sP, sQ, mg, ng, lane, hgrp);
        __syncthreads();

        float acc[32];
#pragma unroll
        for (int i = 0; i < 32; i++) acc[i] = 0.f;
        gemm_gb<8, 2, 4, 8, false>(sbase + T_BUF(p), 0, gw1,
                                   0, 16, ng * 4, mg * 32, acc, lane);
        // h2 -> buf p^1 (writes other buffer; no pre-sync needed)
        epi<false, true>(sm, T_BUF(p ^ 1), acc, sb1, 0.f, sP, sQ, mg, ng, lane, hgrp);
        __syncthreads();

#pragma unroll
        for (int i = 0; i < 32; i++) acc[i] = 0.f;
        gemm_gb<8, 2, 4, 8, false>(sbase + T_BUF(p ^ 1), 0, gw2,
                                   0, 16, ng * 4, mg * 32, acc, lane);
        // h3 -> buf p
        epi<false, true>(sm, T_BUF(p), acc, sb2, 0.f, sP, sQ, mg, ng, lane, hgrp);
        __syncthreads();

        // y += (h3/16) @ W3 (warps with ng<2; nblk = ng selects 8-col block of N=16)
        if (ng < 2) {
            gemm_gb<8, 2, 1, 8, false>(sbase + T_BUF(p), 0, gw3,
                                       0, 2, ng, mg * 32, y, lane);
        }
        p ^= 1;
        powv *= 32.f;
    }

    // ---- scatter (pixel shuffle); y_true = 16*y, out = 0.25*sum + b3 = 4*y + b3 ----
    if (ng < 2) {
        const int rq = lane >> 2, nq = (lane & 3) * 2;
#pragma unroll
        for (int mt = 0; mt < 2; mt++)
#pragma unroll
            for (int half = 0; half < 2; half++)
#pragma unroll
                for (int j = 0; j < 2; j++) {
                    int n = ng * 8 + nq + j;
                    if (n < 12) {
                        int r = mg * 32 + mt * 16 + rq + half * 8;
                        float val = 4.0f * y[mt * 4 + half * 2 + j] + sb3[n];
                        int hi = hgrp * 2 + (r >> 5), wi = r & 31;
                        int rgb = n >> 2, pr = (n >> 1) & 1, qc = n & 1;
                        outp[rgb * 200704 + ahi * 28672 + awi * 4096 +
                             (2 * hi + pr) * 64 + (2 * wi + qc)] = val;
                    }
                }
    }
}

extern "C" void kernel_launch(void* const* d_in, const int* in_sizes, int n_in,
                              void* d_out, int out_size) {
    (void)in_sizes; (void)n_in; (void)out_size;
    const float* inp = (const float*)d_in[0];
    const float* W0  = (const float*)d_in[1];
    const float* b0  = (const float*)d_in[2];
    const float* W1  = (const float*)d_in[3];
    const float* b1  = (const float*)d_in[4];
    const float* W2  = (const float*)d_in[5];
    const float* b2  = (const float*)d_in[6];
    const float* W3  = (const float*)d_in[7];
    const float* b3  = (const float*)d_in[8];
    float* outp = (float*)d_out;

    const int prep_tasks = 90112 + 16384 + 16384 + 2048;
    prep_kernel<<<(prep_tasks + 255) / 256, 256>>>(W0, W1, W2, W3);

    cudaFuncSetAttribute(inr_hmma_kernel, cudaFuncAttributeMaxDynamicSharedMemorySize, SMEM_BYTES);
    inr_hmma_kernel<<<784, TPB, SMEM_BYTES>>>(inp, W0, b0, b1, b2, b3, outp);
}

// round 11
// speedup vs baseline: 2.0799x; 1.2391x over previous
#include <cuda_runtime.h>
#include <cuda_fp16.h>
#include <stdint.h>

#define TPB 256

// ---------------- smem layout (bytes) ----------------
// Branch-phase double-buffered A tiles (hi only): [64 rows][256B] = 16 KB each
#define T_BUF(b)  ((b) * 16384)
// Phase-A chunk buffers alias the same region: [64 rows][128B] = 8 KB each (1-term)
#define OFF_SB0   32768
#define OFF_SB1   33280
#define OFF_SB2   33792
#define OFF_SP    34304
#define OFF_SQ    34816
#define OFF_SB3   35328    // 64 B
#define OFF_LUT   35392    // 648 * 4 = 2592
#define SMEM_BYTES 40960

// activation pre-scale (keeps branch-3 h1 within fp16 range)
#define ASCL   0.0625f     // 1/16
#define ASCL_I 16.0f

// ---------------- device images ----------------
// Zero-padded input: [8 ch][9 a1][9 a2][34 h][34 w]
__device__ __align__(16) float gInpP[749088];
// Single-fp16 B-fragment packed (uint2 per lane entry):
//   entry index = (kblk * nbStride + nblk) * 32 + lane,  lane = (n&7)*4 + ((k>>1)&3)
//   half within entry: ((k>>3)&1)*2 + (k&1)
__device__ __align__(16) __half gW0[90112];  // 704 x 128 (44 kblk x 16 nblk)
__device__ __align__(16) __half gW1[16384];  // 128 x 128 (8 x 16)
__device__ __align__(16) __half gW2[16384];
__device__ __align__(16) __half gW3[2048];   // 128 x 16 (8 x 2)

// ---------------- asm helpers ----------------
__device__ __forceinline__ uint32_t smem_u32(const void* p) {
    uint32_t a;
    asm("{ .reg .u64 t; cvta.to.shared.u64 t, %1; cvt.u32.u64 %0, t; }" : "=r"(a) : "l"(p));
    return a;
}
__device__ __forceinline__ void ldmx4(uint32_t r[4], uint32_t addr) {
    asm volatile("ldmatrix.sync.aligned.m8n8.x4.shared.b16 {%0,%1,%2,%3}, [%4];"
        : "=r"(r[0]), "=r"(r[1]), "=r"(r[2]), "=r"(r[3]) : "r"(addr));
}
__device__ __forceinline__ void mma16816(float* d, const uint32_t a[4], uint32_t b0, uint32_t b1) {
    asm volatile("mma.sync.aligned.m16n8k16.row.col.f32.f16.f16.f32 "
        "{%0,%1,%2,%3}, {%4,%5,%6,%7}, {%8,%9}, {%0,%1,%2,%3};"
        : "+f"(d[0]), "+f"(d[1]), "+f"(d[2]), "+f"(d[3])
        : "r"(a[0]), "r"(a[1]), "r"(a[2]), "r"(a[3]), "r"(b0), "r"(b1));
}

// GEMM: A (fp16, 1-term) from swizzled smem via ldmatrix, B uint2 frags from global.
// Warp computes rows [mrow, mrow+16*MT) x cols [nblk0*8, (nblk0+NT)*8).
template<int KS, int MT, int NT, int RLOG>
__device__ __forceinline__ void gemm_gb(uint32_t aBuf,
    const uint2* __restrict__ gB,
    int kblk0, int nbStride, int nblk0, int mrow, float* acc, int lane)
{
    const int rA = mrow + (lane & 15);
    const int selA = lane >> 4;
    const uint32_t aRow = aBuf + (rA << RLOG);
    const int xorA = rA & 7;
    const uint2* b = gB + (kblk0 * nbStride + nblk0) * 32 + lane;
#pragma unroll
    for (int ks = 0; ks < KS; ks++) {
        const uint32_t offA = ((uint32_t)(((ks * 2 + selA) ^ xorA))) << 4;
        uint32_t ah[MT][4];
#pragma unroll
        for (int mt = 0; mt < MT; mt++)
            ldmx4(ah[mt], aRow + (mt << (RLOG + 4)) + offA);
        uint2 bv[NT];
#pragma unroll
        for (int nt = 0; nt < NT; nt++) bv[nt] = b[nt * 32];
        b += nbStride * 32;
#pragma unroll
        for (int nt = 0; nt < NT; nt++)
#pragma unroll
            for (int mt = 0; mt < MT; mt++)
                mma16816(acc + (mt * NT + nt) * 4, ah[mt], bv[nt].x, bv[nt].y);
    }
}

// epilogue: D frags (ASCL_I*acc + bias [+cell term]) -> relu -> fp16 (xASCL) -> smem hi tile
template<bool EXTRA, bool RESCALE>
__device__ __forceinline__ void epi(char* sm, uint32_t dstOff, const float* acc, const float* bias,
                                    float powv, const float* sP, const float* sQ,
                                    int mg, int ng, int lane, int hgrp)
{
    const int rq = lane >> 2, nq = (lane & 3) * 2;
#pragma unroll
    for (int mt = 0; mt < 2; mt++) {
#pragma unroll
        for (int nt = 0; nt < 4; nt++) {
            int n = ng * 32 + nt * 8 + nq;
            float bb0 = bias[n], bb1 = bias[n + 1];
            float e0 = 0.f, e1 = 0.f;
            if (EXTRA) { e0 = fmaf(powv, sP[n], sQ[n]); e1 = fmaf(powv, sP[n + 1], sQ[n + 1]); }
            const float* a = acc + (mt * 4 + nt) * 4;
#pragma unroll
            for (int half = 0; half < 2; half++) {
                int r = mg * 32 + mt * 16 + rq + half * 8;
                float av0 = RESCALE ? ASCL_I * a[half * 2 + 0] : a[half * 2 + 0];
                float av1 = RESCALE ? ASCL_I * a[half * 2 + 1] : a[half * 2 + 1];
                float v0 = av0 + bb0;
                float v1 = av1 + bb1;
                if (EXTRA) {
                    float s = 1.f;
                    if (hgrp == 0 && r < 4) s = (r < 2) ? 0.0625f : (2.f / 7.f);
                    v0 += s * e0; v1 += s * e1;
                }
                v0 = fmaxf(v0, 0.f) * ASCL;
                v1 = fmaxf(v1, 0.f) * ASCL;
                __half2 hp = __floats2half2_rn(v0, v1);
                int off = (r << 8) + ((((n >> 3) ^ (r & 7)) << 4)) + (n & 7) * 2;
                *(uint32_t*)(sm + dstOff + off) = *(uint32_t*)&hp;
            }
        }
    }
}

// ---------------- prep kernel: padded input + fp16 B-frag weights ----------------
__device__ __forceinline__ void pack_frag(__half* dst, float v, int k, int n, int nbStride) {
    int entry = ((k >> 4) * nbStride + (n >> 3)) * 32 + (n & 7) * 4 + ((k >> 1) & 3);
    int sub = ((k >> 3) & 1) * 2 + (k & 1);
    dst[entry * 4 + sub] = __float2half_rn(v);
}

__global__ void prep_kernel(const float* __restrict__ inp,
                            const float* __restrict__ W0, const float* __restrict__ W1,
                            const float* __restrict__ W2, const float* __restrict__ W3) {
    int idx = blockIdx.x * 256 + threadIdx.x;
    const int nP = 749088, n0 = 90112, n1 = 16384, n2 = 16384, n3 = 2048;
    if (idx < nP) {
        int w1 = idx % 34, h1 = (idx / 34) % 34;
        int a2 = (idx / 1156) % 9, a1 = (idx / 10404) % 9, ch = idx / 93636;
        bool ok = (a1 >= 1 && a1 <= 7 && a2 >= 1 && a2 <= 7 &&
                   h1 >= 1 && h1 <= 32 && w1 >= 1 && w1 <= 32);
        gInpP[idx] = ok ? inp[ch * 50176 + (a1 - 1) * 7168 + (a2 - 1) * 1024
                              + (h1 - 1) * 32 + (w1 - 1)] : 0.f;
    } else if (idx < nP + n0) {
        int r = idx - nP, k = r >> 7, n = r & 127;
        float v = (k < 648) ? W0[k * 128 + n] : 0.f;
        pack_frag(gW0, v, k, n, 16);
    } else if (idx < nP + n0 + n1) {
        int r = idx - nP - n0, k = r >> 7, n = r & 127;
        pack_frag(gW1, W1[k * 128 + n], k, n, 16);
    } else if (idx < nP + n0 + n1 + n2) {
        int r = idx - nP - n0 - n1, k = r >> 7, n = r & 127;
        pack_frag(gW2, W2[k * 128 + n], k, n, 16);
    } else if (idx < nP + n0 + n1 + n2 + n3) {
        int r = idx - nP - n0 - n1 - n2, k = r >> 4, n = r & 15;
        float v = (n < 12) ? W3[k * 12 + n] : 0.f;
        pack_frag(gW3, v, k, n, 2);
    }
}

// ---------------- main kernel ----------------
__global__ __launch_bounds__(TPB, 2)
void inr_hmma_kernel(const float* __restrict__ W0,
                     const float* __restrict__ b0g, const float* __restrict__ b1g,
                     const float* __restrict__ b2g, const float* __restrict__ b3g,
                     float* __restrict__ outp) {
    extern __shared__ char sm[];
    const uint32_t sbase = smem_u32(sm);
    const int tid = threadIdx.x;
    const int lane = tid & 31, w = tid >> 5;
    const int mg = w >> 2, ng = w & 3;      // 2 m-groups (32 rows) x 4 n-groups (32 cols)

    const int blk = blockIdx.x;
    const int ablk = blk >> 4, hgrp = blk & 15;   // 64 rows = 2 h-rows
    const int ahi = ablk / 7, awi = ablk % 7;

    float* sb0 = (float*)(sm + OFF_SB0);
    float* sb1 = (float*)(sm + OFF_SB1);
    float* sb2 = (float*)(sm + OFF_SB2);
    float* sP  = (float*)(sm + OFF_SP);
    float* sQ  = (float*)(sm + OFF_SQ);
    float* sb3 = (float*)(sm + OFF_SB3);
    int*   lut = (int*)(sm + OFF_LUT);

    for (int c = tid; c < 128; c += TPB) {
        sb0[c] = b0g[c]; sb1[c] = b1g[c]; sb2[c] = b2g[c];
        sP[c] = W0[716 * 128 + c] + W0[717 * 128 + c];
        sQ[c] = W0[718 * 128 + c] + W0[719 * 128 + c];
    }
    if (tid < 12) sb3[tid] = b3g[tid];
    for (int k = tid; k < 648; k += TPB) {
        int aj = k % 3, ai = (k / 3) % 3, kj = (k / 9) % 3, ki = (k / 27) % 3, ch = k / 81;
        lut[k] = ch * 93636 + ai * 10404 + aj * 1156 + ki * 34 + kj;
    }
    __syncthreads();

    const uint2* gw0 = (const uint2*)gW0;
    const uint2* gw1 = (const uint2*)gW1;
    const uint2* gw2 = (const uint2*)gW2;
    const uint2* gw3 = (const uint2*)gW3;

    // ================= Phase A: base = q_feat @ W0 (11 chunks of K=64, ping-pong, 1-term) ====
    float base_[32];
#pragma unroll
    for (int i = 0; i < 32; i++) base_[i] = 0.f;

    const int gm = tid & 63;          // row (position)
    const int gstrip = tid >> 6;      // k-pair strip
    // padded-image base offset for this thread's position
    const int ibase = ahi * 10404 + awi * 1156 + hgrp * 68
                    + (gm >> 5) * 34 + (gm & 31);

    auto gather = [&](int c, bool check) {
        char* dh = sm + T_BUF(c & 1);
#pragma unroll
        for (int q = 0; q < 8; q++) {
            int kp = gstrip * 8 + q;
            int kk = c * 64 + kp * 2;
            float v0, v1;
            if (!check) {
                v0 = gInpP[ibase + lut[kk]];
                v1 = gInpP[ibase + lut[kk + 1]];
            } else {
                v0 = (kk < 648) ? gInpP[ibase + lut[kk]] : 0.f;
                v1 = (kk + 1 < 648) ? gInpP[ibase + lut[kk + 1]] : 0.f;
            }
            __half2 hp = __floats2half2_rn(v0, v1);
            int off = gm * 128 + ((((kp >> 2) ^ (gm & 7)) << 4)) + (kp & 3) * 4;
            *(uint32_t*)(dh + off) = *(uint32_t*)&hp;
        }
    };

    gather(0, false);
    __syncthreads();
    for (int c = 0; c < 11; c++) {
        if (c < 10) gather(c + 1, c + 1 == 10);
        gemm_gb<4, 2, 4, 7>(sbase + T_BUF(c & 1), gw0,
                            c * 4, 16, ng * 4, mg * 32, base_, lane);
        __syncthreads();
    }

    // ================= 4 branches (ping-pong hi-only activation tiles, 1-term) =================
    float y[8];
#pragma unroll
    for (int i = 0; i < 8; i++) y[i] = 0.f;
    float powv = 32.f;
    int p = 0;

    for (int br = 0; br < 4; br++) {
        // h1 = relu(base + b0 + s*(powv*P + Q)) -> buf p   (base unscaled: RESCALE=false)
        epi<true, false>(sm, T_BUF(p), base_, sb0, powv, sP, sQ, mg, ng, lane, hgrp);
        __syncthreads();

        float acc[32];
#pragma unroll
        for (int i = 0; i < 32; i++) acc[i] = 0.f;
        gemm_gb<8, 2, 4, 8>(sbase + T_BUF(p), gw1, 0, 16, ng * 4, mg * 32, acc, lane);
        // h2 -> buf p^1 (writes other buffer; no pre-sync needed)
        epi<false, true>(sm, T_BUF(p ^ 1), acc, sb1, 0.f, sP, sQ, mg, ng, lane, hgrp);
        __syncthreads();

#pragma unroll
        for (int i = 0; i < 32; i++) acc[i] = 0.f;
        gemm_gb<8, 2, 4, 8>(sbase + T_BUF(p ^ 1), gw2, 0, 16, ng * 4, mg * 32, acc, lane);
        // h3 -> buf p
        epi<false, true>(sm, T_BUF(p), acc, sb2, 0.f, sP, sQ, mg, ng, lane, hgrp);
        __syncthreads();

        // y += (h3/16) @ W3 (warps with ng<2; nblk = ng selects 8-col block of N=16)
        if (ng < 2) {
            gemm_gb<8, 2, 1, 8>(sbase + T_BUF(p), gw3, 0, 2, ng, mg * 32, y, lane);
        }
        p ^= 1;
        powv *= 32.f;
    }

    // ---- scatter (pixel shuffle); y_true = 16*y, out = 0.25*sum + b3 = 4*y + b3 ----
    if (ng < 2) {
        const int rq = lane >> 2, nq = (lane & 3) * 2;
#pragma unroll
        for (int mt = 0; mt < 2; mt++)
#pragma unroll
            for (int half = 0; half < 2; half++)
#pragma unroll
                for (int j = 0; j < 2; j++) {
                    int n = ng * 8 + nq + j;
                    if (n < 12) {
                        int r = mg * 32 + mt * 16 + rq + half * 8;
                        float val = 4.0f * y[mt * 4 + half * 2 + j] + sb3[n];
                        int hi = hgrp * 2 + (r >> 5), wi = r & 31;
                        int rgb = n >> 2, pr = (n >> 1) & 1, qc = n & 1;
                        outp[rgb * 200704 + ahi * 28672 + awi * 4096 +
                             (2 * hi + pr) * 64 + (2 * wi + qc)] = val;
                    }
                }
    }
}

extern "C" void kernel_launch(void* const* d_in, const int* in_sizes, int n_in,
                              void* d_out, int out_size) {
    (void)in_sizes; (void)n_in; (void)out_size;
    const float* inp = (const float*)d_in[0];
    const float* W0  = (const float*)d_in[1];
    const float* b0  = (const float*)d_in[2];
    const float* W1  = (const float*)d_in[3];
    const float* b1  = (const float*)d_in[4];
    const float* W2  = (const float*)d_in[5];
    const float* b2  = (const float*)d_in[6];
    const float* W3  = (const float*)d_in[7];
    const float* b3  = (const float*)d_in[8];
    float* outp = (float*)d_out;

    const int prep_tasks = 749088 + 90112 + 16384 + 16384 + 2048;
    prep_kernel<<<(prep_tasks + 255) / 256, 256>>>(inp, W0, W1, W2, W3);

    cudaFuncSetAttribute(inr_hmma_kernel, cudaFuncAttributeMaxDynamicSharedMemorySize, SMEM_BYTES);
    inr_hmma_kernel<<<784, TPB, SMEM_BYTES>>>(W0, b0, b1, b2, b3, outp);
}